// round 3
// baseline (speedup 1.0000x reference)
#include <cuda_runtime.h>
#include <cstdint>

#define BB   64
#define LL   512
#define EE   128
#define CPG  256     // channels per kernel-size group
#define TCT  768     // total channels (3 groups)
#define OUTW 2304    // 3 segments * 768

// ---- scratch (static __device__: allocation-free) ----
__device__ __align__(16) float g_emb[BB * LL * EE];            // gathered embeddings [b][l][e]
__device__ __align__(16) float g_wT[(3 + 5 + 7) * EE * CPG];   // transposed weights [k][e][c]
__device__ __align__(16) float g_conv[(size_t)BB * TCT * LL];  // conv+bias+relu, [b][c][l]
__device__ int g_segpos[BB][3];                                // first occurrence of tokens 1,2,3

static const int W3SZ = 3 * EE * CPG;   // 98304
static const int W5SZ = 5 * EE * CPG;   // 163840

// --------------------------------------------------------------------------
// prep: segment boundaries
// --------------------------------------------------------------------------
__global__ void prep_kernel(const int* __restrict__ inp) {
    __shared__ int fpos[3];
    const int b = blockIdx.x;
    const int tid = threadIdx.x;
    if (tid < 3) fpos[tid] = LL - 1;
    __syncthreads();
    for (int l = tid; l < LL; l += blockDim.x) {
        int tok = inp[b * LL + l];
        if (tok >= 1 && tok <= 3) atomicMin(&fpos[tok - 1], l);
    }
    __syncthreads();
    if (tid < 3) g_segpos[b][tid] = fpos[tid];
}

// --------------------------------------------------------------------------
// gather: emb_weight[inputs] -> g_emb  (coalesced float4)
// --------------------------------------------------------------------------
__global__ void gather_kernel(const int* __restrict__ inp, const float* __restrict__ emb) {
    int idx = blockIdx.x * blockDim.x + threadIdx.x;   // over B*L*32 float4s
    int row = idx >> 5;
    int q = idx & 31;
    int tok = inp[row];
    reinterpret_cast<float4*>(g_emb)[idx] =
        reinterpret_cast<const float4*>(emb + (size_t)tok * EE)[q];
}

// --------------------------------------------------------------------------
// weight transpose: src[c][k][e] (c-major) -> g_wT[dstoff + (k*E+e)*CPG + c]
// --------------------------------------------------------------------------
__global__ void wtrans_kernel(const float* __restrict__ src, int KE, int dstoff) {
    int r = blockIdx.x;    // 0..KE-1  (= k*E+e)
    int c = threadIdx.x;   // 0..255
    g_wT[dstoff + r * CPG + c] = src[c * KE + r];
}

// --------------------------------------------------------------------------
// conv + bias + relu -> g_conv   (plain scalar float math, no asm)
// grid: (Ltiles=8, Ctiles=2, B=64), 256 threads
// thread (tx = tid&15, ty = tid>>4): 4 L-positions (ty*4+mi), 8 channels
// channel map: c = cbase + 32*j + 2*tx + {0,1}, j=0..3
// --------------------------------------------------------------------------
template <int K>
__global__ void __launch_bounds__(256) conv_plain(const float* __restrict__ bias,
                                                  int woff, int gbase) {
    constexpr int LO = (K - 1) / 2;
    constexpr int AROWS = 64 + K - 1;
    constexpr int APAD = 132;
    extern __shared__ float smem[];
    float* As = smem;                    // AROWS x APAD
    float* Ws = smem + AROWS * APAD;     // (K*8) x 128
    const float* wT = g_wT + woff;

    const int tid = threadIdx.x;
    const int tx = tid & 15;
    const int ty = tid >> 4;
    const int ty4 = ty * 4;
    const int lbase = blockIdx.x * 64;
    const int cbase = blockIdx.y * 128;
    const int b = blockIdx.z;

    // --- stage embedding tile (with halo, zero-padded at sequence ends) ---
    const float4* embr = reinterpret_cast<const float4*>(g_emb + (size_t)b * LL * EE);
    for (int i = tid; i < AROWS * 32; i += 256) {
        int r = i >> 5, q = i & 31;
        int gl = lbase - LO + r;
        float4 v = make_float4(0.f, 0.f, 0.f, 0.f);
        if (gl >= 0 && gl < LL) v = embr[gl * 32 + q];
        *reinterpret_cast<float4*>(&As[r * APAD + q * 4]) = v;
    }

    float acc[4][8];
#pragma unroll
    for (int mi = 0; mi < 4; mi++)
#pragma unroll
        for (int jj = 0; jj < 8; jj++) acc[mi][jj] = 0.0f;

    for (int e0 = 0; e0 < EE; e0 += 8) {
        __syncthreads();
        // stage weight chunk: Ws[(k*8+e8)*128 + c] = wT[(k*E + e0+e8)*CPG + cbase + c]
        for (int i = tid; i < K * 8 * 32; i += 256) {
            int r = i >> 5, q = i & 31;       // r = k*8 + e8
            int k = r >> 3, e8 = r & 7;
            float4 wv = *reinterpret_cast<const float4*>(
                &wT[(size_t)(k * EE + e0 + e8) * CPG + cbase + q * 4]);
            *reinterpret_cast<float4*>(&Ws[r * 128 + q * 4]) = wv;
        }
        __syncthreads();

#pragma unroll
        for (int e8 = 0; e8 < 8; e8++) {
            float a[K + 3];
#pragma unroll
            for (int rr = 0; rr < K + 3; rr++)
                a[rr] = As[(ty4 + rr) * APAD + e0 + e8];
#pragma unroll
            for (int k = 0; k < K; k++) {
                const float2* wrow =
                    reinterpret_cast<const float2*>(&Ws[(k * 8 + e8) * 128]);
                float2 w2[4];
#pragma unroll
                for (int j = 0; j < 4; j++) w2[j] = wrow[j * 16 + tx];
#pragma unroll
                for (int mi = 0; mi < 4; mi++)
#pragma unroll
                    for (int j = 0; j < 4; j++) {
                        acc[mi][2 * j]     += a[mi + k] * w2[j].x;
                        acc[mi][2 * j + 1] += a[mi + k] * w2[j].y;
                    }
            }
        }
    }

    // --- epilogue: bias + relu -> smem transpose -> coalesced global store ---
    __syncthreads();                      // done with As/Ws
    float* Os = smem;                     // 128 x 65 (padded)
#pragma unroll
    for (int j = 0; j < 4; j++) {
        int c0 = cbase + j * 32 + tx * 2;
        float b0 = bias[c0], b1 = bias[c0 + 1];
        int cl0 = j * 32 + tx * 2;
#pragma unroll
        for (int mi = 0; mi < 4; mi++) {
            Os[cl0 * 65 + ty4 + mi]       = fmaxf(acc[mi][2 * j] + b0, 0.0f);
            Os[(cl0 + 1) * 65 + ty4 + mi] = fmaxf(acc[mi][2 * j + 1] + b1, 0.0f);
        }
    }
    __syncthreads();
    // write 128 channel-rows x 64 l, float4 per thread-iter
    for (int i = tid; i < 128 * 16; i += 256) {
        int c = i >> 4, q = i & 15;
        float4 v;
        v.x = Os[c * 65 + q * 4 + 0];
        v.y = Os[c * 65 + q * 4 + 1];
        v.z = Os[c * 65 + q * 4 + 2];
        v.w = Os[c * 65 + q * 4 + 3];
        *reinterpret_cast<float4*>(
            &g_conv[((size_t)b * TCT + gbase + cbase + c) * LL + lbase + q * 4]) = v;
    }
}

// --------------------------------------------------------------------------
// pool: one warp per (b, t, c) -> out[b, t*768 + c]
// --------------------------------------------------------------------------
__global__ void pool_kernel(float* __restrict__ out) {
    int gw = (blockIdx.x * blockDim.x + threadIdx.x) >> 5;  // global warp id
    int lane = threadIdx.x & 31;
    int c = gw % TCT;
    int t = (gw / TCT) % 3;
    int b = gw / (TCT * 3);
    int hi = g_segpos[b][t];                       // inclusive
    int lo = (t == 0) ? 0 : g_segpos[b][t - 1];    // inclusive (shared endpoint)
    const float* row = g_conv + ((size_t)b * TCT + c) * LL;
    float m = -1e30f;
    for (int l = lo + lane; l <= hi; l += 32) m = fmaxf(m, row[l]);
#pragma unroll
    for (int o = 16; o; o >>= 1) m = fmaxf(m, __shfl_xor_sync(0xffffffffu, m, o));
    if (lane == 0) out[b * OUTW + t * TCT + c] = m;
}

// --------------------------------------------------------------------------
extern "C" void kernel_launch(void* const* d_in, const int* in_sizes, int n_in,
                              void* d_out, int out_size) {
    // map by element count; positional fallback
    const int* inp = nullptr;
    const float *emb = nullptr, *w3 = nullptr, *w5 = nullptr, *w7 = nullptr;
    const float* biases[3] = {nullptr, nullptr, nullptr};
    int nb = 0;
    for (int i = 0; i < n_in; i++) {
        switch (in_sizes[i]) {
            case 32768:   inp = (const int*)d_in[i];   break;
            case 6400000: emb = (const float*)d_in[i]; break;
            case 98304:   w3 = (const float*)d_in[i];  break;
            case 163840:  w5 = (const float*)d_in[i];  break;
            case 229376:  w7 = (const float*)d_in[i];  break;
            case 256:     if (nb < 3) biases[nb++] = (const float*)d_in[i]; break;
            default: break;
        }
    }
    if (!inp || !emb || !w3 || !w5 || !w7 || nb != 3) {
        inp = (const int*)d_in[0];
        emb = (const float*)d_in[1];
        w3 = (const float*)d_in[2];  biases[0] = (const float*)d_in[3];
        w5 = (const float*)d_in[4];  biases[1] = (const float*)d_in[5];
        w7 = (const float*)d_in[6];  biases[2] = (const float*)d_in[7];
    }
    const float* b3 = biases[0];
    const float* b5 = biases[1];
    const float* b7 = biases[2];
    float* out = (float*)d_out;
    (void)out_size;

    const int smem3 = (66 * 132 + 3 * 8 * 128) * 4;   // 47136 (>= 128*65*4 = 33280)
    const int smem5 = (68 * 132 + 5 * 8 * 128) * 4;   // 56384
    const int smem7 = (70 * 132 + 7 * 8 * 128) * 4;   // 65632
    cudaFuncSetAttribute(conv_plain<3>, cudaFuncAttributeMaxDynamicSharedMemorySize, smem3);
    cudaFuncSetAttribute(conv_plain<5>, cudaFuncAttributeMaxDynamicSharedMemorySize, smem5);
    cudaFuncSetAttribute(conv_plain<7>, cudaFuncAttributeMaxDynamicSharedMemorySize, smem7);

    prep_kernel<<<BB, 256>>>(inp);
    gather_kernel<<<(BB * LL * 32) / 256, 256>>>(inp, emb);
    wtrans_kernel<<<3 * EE, 256>>>(w3, 3 * EE, 0);
    wtrans_kernel<<<5 * EE, 256>>>(w5, 5 * EE, W3SZ);
    wtrans_kernel<<<7 * EE, 256>>>(w7, 7 * EE, W3SZ + W5SZ);

    dim3 grid(8, 2, BB);
    conv_plain<3><<<grid, 256, smem3>>>(b3, 0, 0);
    conv_plain<5><<<grid, 256, smem5>>>(b5, W3SZ, 256);
    conv_plain<7><<<grid, 256, smem7>>>(b7, W3SZ + W5SZ, 512);

    pool_kernel<<<(BB * 3 * TCT * 32) / 256, 256>>>(out);
}

// round 4
// speedup vs baseline: 1.1579x; 1.1579x over previous
#include <cuda_runtime.h>
#include <cstdint>

#define BB   64
#define LL   512
#define EE   128
#define CPG  256     // channels per kernel-size group
#define TCT  768     // total channels (3 groups)
#define OUTW 2304    // 3 segments * 768

// ---- scratch (static __device__: allocation-free) ----
__device__ __align__(16) float g_emb[BB * LL * EE];                  // gathered embeddings
__device__ __align__(16) float g_wT[(3 + 5 + 7) * EE * CPG];         // transposed weights [k][e][c]
__device__ int g_segpos[BB][3];                                      // first occurrence of tokens 1,2,3

static const int W3SZ = 3 * EE * CPG;   // 98304
static const int W5SZ = 5 * EE * CPG;   // 163840

// --------------------------------------------------------------------------
// prep: segment boundaries + zero output (atomicMax base)
// --------------------------------------------------------------------------
__global__ void prep_kernel(const int* __restrict__ inp, float* __restrict__ out) {
    __shared__ int fpos[3];
    const int b = blockIdx.x;
    const int tid = threadIdx.x;
    if (tid < 3) fpos[tid] = LL - 1;
    __syncthreads();
    for (int l = tid; l < LL; l += blockDim.x) {
        int tok = inp[b * LL + l];
        if (tok >= 1 && tok <= 3) atomicMin(&fpos[tok - 1], l);
    }
    __syncthreads();
    if (tid < 3) g_segpos[b][tid] = fpos[tid];
    for (int i = tid; i < OUTW; i += blockDim.x) out[b * OUTW + i] = 0.0f;
}

// --------------------------------------------------------------------------
// gather: emb_weight[inputs] -> g_emb  (coalesced float4)
// --------------------------------------------------------------------------
__global__ void gather_kernel(const int* __restrict__ inp, const float* __restrict__ emb) {
    int idx = blockIdx.x * blockDim.x + threadIdx.x;   // over B*L*32 float4s
    int row = idx >> 5;
    int q = idx & 31;
    int tok = inp[row];
    reinterpret_cast<float4*>(g_emb)[idx] =
        reinterpret_cast<const float4*>(emb + (size_t)tok * EE)[q];
}

// --------------------------------------------------------------------------
// weight transpose: src[c][k][e] (c-major) -> g_wT[dstoff + (k*E+e)*CPG + c]
// --------------------------------------------------------------------------
__global__ void wtrans_kernel(const float* __restrict__ src, int KE, int dstoff) {
    int r = blockIdx.x;    // 0..KE-1  (= k*E+e)
    int c = threadIdx.x;   // 0..255
    g_wT[dstoff + r * CPG + c] = src[c * KE + r];
}

// --------------------------------------------------------------------------
// conv + bias + relu + fused segmented max  (f32x2 packed FFMA mainloop)
// grid: (Ltiles=8, Ctiles=2, B=64), 256 threads
// thread (tx = tid&15, ty = tid>>4): 4 L-positions (ty*4+mi), 8 channels
// channel map: c = cbase + 32*j + 2*tx + {0,1}, j=0..3  (f32x2 channel pairs)
// --------------------------------------------------------------------------
template <int K>
__global__ void __launch_bounds__(256) conv_kernel(const float* __restrict__ bias,
                                                   float* __restrict__ out,
                                                   int woff, int gbase) {
    constexpr int LO = (K - 1) / 2;
    constexpr int AROWS = 64 + K - 1;
    constexpr int APAD = 132;            // 132*4 = 528 B rows: 16B aligned, bank-shifted
    extern __shared__ float smem[];
    float* As = smem;                    // AROWS x APAD
    float* Ws = smem + AROWS * APAD;     // (K*8) x 128
    const float* wT = g_wT + woff;

    const int tid = threadIdx.x;
    const int tx = tid & 15;
    const int ty = tid >> 4;
    const int ty4 = ty * 4;
    const int lbase = blockIdx.x * 64;
    const int cbase = blockIdx.y * 128;
    const int b = blockIdx.z;

    // --- stage embedding tile (with halo, zero-padded at sequence ends) ---
    const float4* embr = reinterpret_cast<const float4*>(g_emb + (size_t)b * LL * EE);
    for (int i = tid; i < AROWS * 32; i += 256) {
        int r = i >> 5, q = i & 31;
        int gl = lbase - LO + r;
        float4 v = make_float4(0.f, 0.f, 0.f, 0.f);
        if (gl >= 0 && gl < LL) v = embr[gl * 32 + q];
        *reinterpret_cast<float4*>(&As[r * APAD + q * 4]) = v;
    }

    unsigned long long acc[4][4];
#pragma unroll
    for (int mi = 0; mi < 4; mi++)
#pragma unroll
        for (int j = 0; j < 4; j++) acc[mi][j] = 0ull;

    for (int e0 = 0; e0 < EE; e0 += 8) {
        __syncthreads();
        // stage weight chunk: Ws[(k*8+e8)*128 + c] = wT[(k*E + e0+e8)*CPG + cbase + c]
        for (int i = tid; i < K * 8 * 32; i += 256) {
            int r = i >> 5, q = i & 31;       // r = k*8 + e8
            int k = r >> 3, e8 = r & 7;
            float4 wv = *reinterpret_cast<const float4*>(
                &wT[(size_t)(k * EE + e0 + e8) * CPG + cbase + q * 4]);
            *reinterpret_cast<float4*>(&Ws[r * 128 + q * 4]) = wv;
        }
        __syncthreads();

#pragma unroll
        for (int e8 = 0; e8 < 8; e8++) {
            // a values: rows ty4 .. ty4+3+K-1 at column e0+e8, duplicated into f32x2
            unsigned long long a2[K + 3];
#pragma unroll
            for (int rr = 0; rr < K + 3; rr++) {
                float av = As[(ty4 + rr) * APAD + e0 + e8];
                asm("mov.b64 %0, {%1, %1};" : "=l"(a2[rr]) : "f"(av));
            }
#pragma unroll
            for (int k = 0; k < K; k++) {
                const unsigned long long* wrow =
                    reinterpret_cast<const unsigned long long*>(&Ws[(k * 8 + e8) * 128]);
                unsigned long long b2[4];
#pragma unroll
                for (int j = 0; j < 4; j++) b2[j] = wrow[j * 16 + tx];
#pragma unroll
                for (int mi = 0; mi < 4; mi++)
#pragma unroll
                    for (int j = 0; j < 4; j++)
                        asm("fma.rn.f32x2 %0, %1, %2, %0;"
                            : "+l"(acc[mi][j])
                            : "l"(a2[mi + k]), "l"(b2[j]));
            }
        }
    }

    // --- epilogue: bias + relu, segmented max into smem, then global atomicMax ---
    __syncthreads();                       // done reading As/Ws
    int* segm = reinterpret_cast<int*>(smem);   // 3 * 128 ints, reuses As
    for (int i = tid; i < 3 * 128; i += 256) segm[i] = 0;   // FIXED: full 384 coverage

    float v[4][8];
#pragma unroll
    for (int j = 0; j < 4; j++) {
        int c0 = cbase + j * 32 + tx * 2;
        float b0 = bias[c0], b1 = bias[c0 + 1];
#pragma unroll
        for (int mi = 0; mi < 4; mi++) {
            float x, y;
            asm("mov.b64 {%0, %1}, %2;" : "=f"(x), "=f"(y) : "l"(acc[mi][j]));
            v[mi][2 * j] = fmaxf(x + b0, 0.0f);
            v[mi][2 * j + 1] = fmaxf(y + b1, 0.0f);
        }
    }
    int p1 = g_segpos[b][0], p2 = g_segpos[b][1], p3 = g_segpos[b][2];
    int slo[3] = {0, p1, p2};
    int shi[3] = {p1, p2, p3};
    __syncthreads();                       // segm init visible

#pragma unroll
    for (int t = 0; t < 3; t++) {
        bool in[4];
        bool any = false;
#pragma unroll
        for (int mi = 0; mi < 4; mi++) {
            int l = lbase + ty4 + mi;
            in[mi] = (l >= slo[t] && l <= shi[t]);
            any |= in[mi];
        }
        if (!any) continue;
#pragma unroll
        for (int jj = 0; jj < 8; jj++) {
            float m = -1.0f;
#pragma unroll
            for (int mi = 0; mi < 4; mi++)
                if (in[mi]) m = fmaxf(m, v[mi][jj]);
            if (m > 0.0f) {
                int c = (jj >> 1) * 32 + tx * 2 + (jj & 1);
                atomicMax(&segm[t * 128 + c], __float_as_int(m));
            }
        }
    }
    __syncthreads();
    for (int i = tid; i < 3 * 128; i += 256) {   // FIXED: full 384 coverage
        int t = i >> 7, c = i & 127;
        if (segm[i] != 0)
            atomicMax(reinterpret_cast<int*>(&out[(size_t)b * OUTW + t * TCT + gbase + cbase + c]),
                      segm[i]);
    }
}

// --------------------------------------------------------------------------
extern "C" void kernel_launch(void* const* d_in, const int* in_sizes, int n_in,
                              void* d_out, int out_size) {
    // map by element count; positional fallback
    const int* inp = nullptr;
    const float *emb = nullptr, *w3 = nullptr, *w5 = nullptr, *w7 = nullptr;
    const float* biases[3] = {nullptr, nullptr, nullptr};
    int nb = 0;
    for (int i = 0; i < n_in; i++) {
        switch (in_sizes[i]) {
            case 32768:   inp = (const int*)d_in[i];   break;
            case 6400000: emb = (const float*)d_in[i]; break;
            case 98304:   w3 = (const float*)d_in[i];  break;
            case 163840:  w5 = (const float*)d_in[i];  break;
            case 229376:  w7 = (const float*)d_in[i];  break;
            case 256:     if (nb < 3) biases[nb++] = (const float*)d_in[i]; break;
            default: break;
        }
    }
    if (!inp || !emb || !w3 || !w5 || !w7 || nb != 3) {
        inp = (const int*)d_in[0];
        emb = (const float*)d_in[1];
        w3 = (const float*)d_in[2];  biases[0] = (const float*)d_in[3];
        w5 = (const float*)d_in[4];  biases[1] = (const float*)d_in[5];
        w7 = (const float*)d_in[6];  biases[2] = (const float*)d_in[7];
    }
    const float* b3 = biases[0];
    const float* b5 = biases[1];
    const float* b7 = biases[2];
    float* out = (float*)d_out;
    (void)out_size;

    const int smem3 = (66 * 132 + 3 * 8 * 128) * 4;   // 47136
    const int smem5 = (68 * 132 + 5 * 8 * 128) * 4;   // 56384
    const int smem7 = (70 * 132 + 7 * 8 * 128) * 4;   // 65632
    cudaFuncSetAttribute(conv_kernel<3>, cudaFuncAttributeMaxDynamicSharedMemorySize, smem3);
    cudaFuncSetAttribute(conv_kernel<5>, cudaFuncAttributeMaxDynamicSharedMemorySize, smem5);
    cudaFuncSetAttribute(conv_kernel<7>, cudaFuncAttributeMaxDynamicSharedMemorySize, smem7);

    prep_kernel<<<BB, 256>>>(inp, out);
    gather_kernel<<<(BB * LL * 32) / 256, 256>>>(inp, emb);
    wtrans_kernel<<<3 * EE, 256>>>(w3, 3 * EE, 0);
    wtrans_kernel<<<5 * EE, 256>>>(w5, 5 * EE, W3SZ);
    wtrans_kernel<<<7 * EE, 256>>>(w7, 7 * EE, W3SZ + W5SZ);

    dim3 grid(8, 2, BB);
    conv_kernel<3><<<grid, 256, smem3>>>(b3, out, 0, 0);
    conv_kernel<5><<<grid, 256, smem5>>>(b5, out, W3SZ, 256);
    conv_kernel<7><<<grid, 256, smem7>>>(b7, out, W3SZ + W5SZ, 512);
}